// round 9
// baseline (speedup 1.0000x reference)
#include <cuda_runtime.h>
#include <cstdint>

#define N_LEVELS 12
#define LOG2_T 19
#define TBL_SIZE (1u << LOG2_T)
#define TMASK (TBL_SIZE - 1u)
#define N_FEATURES 2
#define N_PTS 1048576

#define P1 2654435761u
#define P2 805459861u

#define SORT_RES 32
#define NB (SORT_RES * SORT_RES * SORT_RES)

#define DENSE_LEVELS 8
#define TOTAL_DENSE 5861806   // sum of Sx*Sy*Sy over levels 0..7 (all even)

__device__ uint32_t g_kr[N_PTS];
__device__ uint32_t g_hist[NB];
__device__ uint32_t g_off[NB];
__device__ float4   g_xs[N_PTS];
__device__ float4   g_dense4[TOTAL_DENSE / 2];   // float2 entries, 16B-aligned

// Per-level dense-grid geometry (r, Sx=r+2 even, SxSy=Sx*(r+1), offset — all even)
#define K_R0 16
#define K_R1 22
#define K_R2 30
#define K_R3 42
#define K_R4 58
#define K_R5 80
#define K_R6 110
#define K_R7 152

__device__ __forceinline__ uint32_t part1by2(uint32_t v) {
    v &= 0x3FFu;
    v = (v | (v << 16)) & 0x030000FFu;
    v = (v | (v << 8))  & 0x0300F00Fu;
    v = (v | (v << 4))  & 0x030C30C3u;
    v = (v | (v << 2))  & 0x09249249u;
    return v;
}

__device__ __forceinline__ uint32_t bucket_key(float px, float py, float pz) {
    uint32_t cx = min((uint32_t)(px * (float)SORT_RES), (uint32_t)(SORT_RES - 1));
    uint32_t cy = min((uint32_t)(py * (float)SORT_RES), (uint32_t)(SORT_RES - 1));
    uint32_t cz = min((uint32_t)(pz * (float)SORT_RES), (uint32_t)(SORT_RES - 1));
    return part1by2(cx) | (part1by2(cy) << 1) | (part1by2(cz) << 2);
}

__global__ void hist_kernel(const float* __restrict__ x) {
    int i = blockIdx.x * blockDim.x + threadIdx.x;
    if (i >= N_PTS) return;
    uint32_t key = bucket_key(x[3 * i], x[3 * i + 1], x[3 * i + 2]);
    uint32_t rank = atomicAdd(&g_hist[key], 1u);
    g_kr[i] = key | (rank << 15);
}

__device__ __forceinline__ uint32_t swz(uint32_t i) {
    return (i & ~31u) | ((i + (i >> 5)) & 31u);
}

__global__ void __launch_bounds__(1024) scan_kernel() {
    extern __shared__ uint32_t sh[];
    __shared__ uint32_t s[1024];
    const int t = threadIdx.x;

    #pragma unroll
    for (int k = 0; k < 32; k++) {
        uint32_t i = (uint32_t)(k * 1024 + t);
        sh[swz(i)] = g_hist[i];
    }
    __syncthreads();

    uint32_t vals[32];
    uint32_t tot = 0;
    #pragma unroll
    for (int k = 0; k < 32; k++) {
        vals[k] = sh[t * 32 + ((k + t) & 31)];
        tot += vals[k];
    }
    s[t] = tot;
    __syncthreads();

    for (int off = 1; off < 1024; off <<= 1) {
        uint32_t v = (t >= off) ? s[t - off] : 0u;
        __syncthreads();
        s[t] += v;
        __syncthreads();
    }

    uint32_t run = s[t] - tot;
    #pragma unroll
    for (int k = 0; k < 32; k++) {
        sh[t * 32 + ((k + t) & 31)] = run;
        run += vals[k];
    }
    __syncthreads();

    #pragma unroll
    for (int k = 0; k < 32; k++) {
        uint32_t i = (uint32_t)(k * 1024 + t);
        g_off[i] = sh[swz(i)];
    }
}

__global__ void scatter_kernel(const float* __restrict__ x) {
    int i = blockIdx.x * blockDim.x + threadIdx.x;
    if (i >= N_PTS) return;
    uint32_t v = g_kr[i];
    uint32_t pos = g_off[v & (NB - 1u)] + (v >> 15);
    float4 p;
    p.x = x[3 * i + 0];
    p.y = x[3 * i + 1];
    p.z = x[3 * i + 2];
    p.w = __uint_as_float((uint32_t)i);
    __stcs(&g_xs[pos], p);
}

// Re-grid one level's hashed table into a dense spatial grid.
// dense[off + cx + cy*Sx + cz*SxSy] = table[level][hash(cx,cy,cz)]
// Values copied verbatim -> encode output bitwise identical.
__global__ void build_dense_kernel(const float* __restrict__ tables,
                                   int level, int r, int Sx, int SxSy,
                                   uint32_t off, uint32_t n)
{
    uint32_t i = blockIdx.x * blockDim.x + threadIdx.x;
    if (i >= n) return;
    uint32_t cz  = i / (uint32_t)SxSy;
    uint32_t rem = i - cz * (uint32_t)SxSy;
    uint32_t cy  = rem / (uint32_t)Sx;
    uint32_t cx  = rem - cy * (uint32_t)Sx;
    if (cx > (uint32_t)r) return;   // padding column, never read
    uint32_t h = (cx ^ (cy * P1) ^ (cz * P2)) & TMASK;
    const float2* __restrict__ tab =
        (const float2*)(tables + (size_t)level * TBL_SIZE * N_FEATURES);
    float2* __restrict__ dense = (float2*)g_dense4;
    dense[off + i] = __ldg(tab + h);
}

__global__ void __launch_bounds__(256, 5) hashgrid_kernel(
    const float* __restrict__ tables,
    float* __restrict__ out)
{
    const int i = blockIdx.x * blockDim.x + threadIdx.x;
    if (i >= N_PTS) return;

    const float4 p = __ldg(&g_xs[i]);
    const float px = p.x;
    const float py = p.y;
    const float pz = p.z;
    const uint32_t j = __float_as_uint(p.w);

    float4* __restrict__ o = (float4*)(out + (size_t)j * (N_LEVELS * N_FEATURES));

    const int res_host[N_LEVELS] = {16, 22, 30, 42, 58, 80, 110, 152, 210, 290, 400, 553};
    // Dense geometry (levels 0..7): Sx=r+2, SxSy=Sx*(r+1), offsets (all even)
    const int dSx[DENSE_LEVELS]   = {18, 24, 32, 44, 60, 82, 112, 154};
    const int dSxSy[DENSE_LEVELS] = {306, 552, 992, 1892, 3540, 6642, 12432, 23562};
    const uint32_t dOff[DENSE_LEVELS] =
        {0u, 5202u, 17898u, 48650u, 130006u, 338866u, 876868u, 2256820u};

    const float2* __restrict__ dense = (const float2*)g_dense4;
    const float4* __restrict__ dense4 = (const float4*)g_dense4;

    float pend0 = 0.0f, pend1 = 0.0f;

    #pragma unroll
    for (int l = 0; l < N_LEVELS; l++) {
        const float res = (float)res_host[l];

        const float sx = px * res;
        const float sy = py * res;
        const float sz = pz * res;
        const float fx = floorf(sx);
        const float fy = floorf(sy);
        const float fz = floorf(sz);
        const float wx = sx - fx;
        const float wy = sy - fy;
        const float wz = sz - fz;

        const uint32_t xi = (uint32_t)fx;
        const uint32_t yi = (uint32_t)fy;
        const uint32_t zi = (uint32_t)fz;

        float2 f000, f100, f010, f110, f001, f101, f011, f111;

        if (l < DENSE_LEVELS) {
            // Spatially-indexed dense grid: warp-local corners share lines.
            const uint32_t Sx   = (uint32_t)dSx[l];
            const uint32_t SxSy = (uint32_t)dSxSy[l];
            const uint32_t base = dOff[l] + xi + yi * Sx + zi * SxSy;

            const uint32_t b00 = base;          // (dy,dz)=(0,0)
            const uint32_t b10 = base + Sx;     // (1,0)
            const uint32_t b01 = base + SxSy;   // (0,1)
            const uint32_t b11 = b10 + SxSy;    // (1,1)

            if ((xi & 1u) == 0u) {
                // even cx: index parity even (Sx, SxSy, off all even)
                // -> dx-pair is one aligned float4, dx=0 in low half.
                const float4 v00 = __ldg(dense4 + (b00 >> 1));
                const float4 v10 = __ldg(dense4 + (b10 >> 1));
                const float4 v01 = __ldg(dense4 + (b01 >> 1));
                const float4 v11 = __ldg(dense4 + (b11 >> 1));
                f000 = make_float2(v00.x, v00.y);  f100 = make_float2(v00.z, v00.w);
                f010 = make_float2(v10.x, v10.y);  f110 = make_float2(v10.z, v10.w);
                f001 = make_float2(v01.x, v01.y);  f101 = make_float2(v01.z, v01.w);
                f011 = make_float2(v11.x, v11.y);  f111 = make_float2(v11.z, v11.w);
            } else {
                f000 = __ldg(dense + b00);  f100 = __ldg(dense + b00 + 1);
                f010 = __ldg(dense + b10);  f110 = __ldg(dense + b10 + 1);
                f001 = __ldg(dense + b01);  f101 = __ldg(dense + b01 + 1);
                f011 = __ldg(dense + b11);  f111 = __ldg(dense + b11 + 1);
            }
        } else {
            // Hashed path (levels 8..11)
            const uint32_t hy0 = yi * P1;
            const uint32_t hy1 = (yi + 1u) * P1;
            const uint32_t hz0 = zi * P2;
            const uint32_t hz1 = (zi + 1u) * P2;
            const uint32_t x0 = xi;
            const uint32_t x1 = xi + 1u;

            const uint32_t m00 = hy0 ^ hz0;
            const uint32_t m10 = hy1 ^ hz0;
            const uint32_t m01 = hy0 ^ hz1;
            const uint32_t m11 = hy1 ^ hz1;

            const uint32_t i000 = (x0 ^ m00) & TMASK;
            const uint32_t i010 = (x0 ^ m10) & TMASK;
            const uint32_t i001 = (x0 ^ m01) & TMASK;
            const uint32_t i011 = (x0 ^ m11) & TMASK;

            const float2* __restrict__ tab =
                (const float2*)(tables + (size_t)l * TBL_SIZE * N_FEATURES);

            if ((xi & 1u) == 0u) {
                const float4* __restrict__ t4 = (const float4*)tab;
                const float4 v00 = __ldg(t4 + (i000 >> 1));
                const float4 v10 = __ldg(t4 + (i010 >> 1));
                const float4 v01 = __ldg(t4 + (i001 >> 1));
                const float4 v11 = __ldg(t4 + (i011 >> 1));

                const bool s00 = (i000 & 1u) != 0u;
                const bool s10 = (i010 & 1u) != 0u;
                const bool s01 = (i001 & 1u) != 0u;
                const bool s11 = (i011 & 1u) != 0u;

                f000 = s00 ? make_float2(v00.z, v00.w) : make_float2(v00.x, v00.y);
                f100 = s00 ? make_float2(v00.x, v00.y) : make_float2(v00.z, v00.w);
                f010 = s10 ? make_float2(v10.z, v10.w) : make_float2(v10.x, v10.y);
                f110 = s10 ? make_float2(v10.x, v10.y) : make_float2(v10.z, v10.w);
                f001 = s01 ? make_float2(v01.z, v01.w) : make_float2(v01.x, v01.y);
                f101 = s01 ? make_float2(v01.x, v01.y) : make_float2(v01.z, v01.w);
                f011 = s11 ? make_float2(v11.z, v11.w) : make_float2(v11.x, v11.y);
                f111 = s11 ? make_float2(v11.x, v11.y) : make_float2(v11.z, v11.w);
            } else {
                const uint32_t i100 = (x1 ^ m00) & TMASK;
                const uint32_t i110 = (x1 ^ m10) & TMASK;
                const uint32_t i101 = (x1 ^ m01) & TMASK;
                const uint32_t i111 = (x1 ^ m11) & TMASK;

                f000 = __ldg(tab + i000);
                f100 = __ldg(tab + i100);
                f010 = __ldg(tab + i010);
                f110 = __ldg(tab + i110);
                f001 = __ldg(tab + i001);
                f101 = __ldg(tab + i101);
                f011 = __ldg(tab + i011);
                f111 = __ldg(tab + i111);
            }
        }

        const float ux = 1.0f - wx;
        const float uy = 1.0f - wy;
        const float uz = 1.0f - wz;

        const float w000 = ux * uy * uz;
        const float w100 = wx * uy * uz;
        const float w010 = ux * wy * uz;
        const float w110 = wx * wy * uz;
        const float w001 = ux * uy * wz;
        const float w101 = wx * uy * wz;
        const float w011 = ux * wy * wz;
        const float w111 = wx * wy * wz;

        float acc0 = w000 * f000.x;
        float acc1 = w000 * f000.y;
        acc0 += w100 * f100.x;  acc1 += w100 * f100.y;
        acc0 += w010 * f010.x;  acc1 += w010 * f010.y;
        acc0 += w110 * f110.x;  acc1 += w110 * f110.y;
        acc0 += w001 * f001.x;  acc1 += w001 * f001.y;
        acc0 += w101 * f101.x;  acc1 += w101 * f101.y;
        acc0 += w011 * f011.x;  acc1 += w011 * f011.y;
        acc0 += w111 * f111.x;  acc1 += w111 * f111.y;

        if ((l & 1) == 0) {
            pend0 = acc0;
            pend1 = acc1;
        } else {
            __stcs(&o[l >> 1], make_float4(pend0, pend1, acc0, acc1));
        }
    }
}

extern "C" void kernel_launch(void* const* d_in, const int* in_sizes, int n_in,
                              void* d_out, int out_size) {
    const float* x      = (const float*)d_in[0];
    const float* tables = (const float*)d_in[1];
    float* out          = (float*)d_out;

    const int threads = 256;
    const int blocks = (N_PTS + threads - 1) / threads;

    static bool attr_set = false;
    if (!attr_set) {
        cudaFuncSetAttribute(scan_kernel,
                             cudaFuncAttributeMaxDynamicSharedMemorySize,
                             NB * sizeof(uint32_t));
        attr_set = true;
    }

    void* hist_ptr = nullptr;
    cudaGetSymbolAddress(&hist_ptr, g_hist);
    cudaMemsetAsync(hist_ptr, 0, NB * sizeof(uint32_t));

    hist_kernel<<<blocks, threads>>>(x);
    scan_kernel<<<1, 1024, NB * sizeof(uint32_t)>>>();
    scatter_kernel<<<blocks, threads>>>(x);

    // Dense re-grid of levels 0..7 (geometry mirrors device tables).
    const int hR[DENSE_LEVELS]    = {16, 22, 30, 42, 58, 80, 110, 152};
    const int hSx[DENSE_LEVELS]   = {18, 24, 32, 44, 60, 82, 112, 154};
    const int hSxSy[DENSE_LEVELS] = {306, 552, 992, 1892, 3540, 6642, 12432, 23562};
    const uint32_t hOff[DENSE_LEVELS] =
        {0u, 5202u, 17898u, 48650u, 130006u, 338866u, 876868u, 2256820u};
    for (int l = 0; l < DENSE_LEVELS; l++) {
        uint32_t n = (uint32_t)hSxSy[l] * (uint32_t)(hR[l] + 1);
        build_dense_kernel<<<(n + 255) / 256, 256>>>(
            tables, l, hR[l], hSx[l], hSxSy[l], hOff[l], n);
    }

    hashgrid_kernel<<<blocks, threads>>>(tables, out);
}

// round 10
// speedup vs baseline: 1.1177x; 1.1177x over previous
#include <cuda_runtime.h>
#include <cstdint>

#define N_LEVELS 12
#define LOG2_T 19
#define TBL_SIZE (1u << LOG2_T)
#define TMASK (TBL_SIZE - 1u)
#define N_FEATURES 2
#define N_PTS 1048576

#define P1 2654435761u
#define P2 805459861u

#define SORT_RES 32
#define NB (SORT_RES * SORT_RES * SORT_RES)

// Dense spatial re-grid of levels 0..6 (18 MB). Level 7+ stays hashed.
#define DENSE_LEVELS 7
#define TOTAL_DENSE 2256820u          // sum of Sx*Sy*Sz, levels 0..6 (even)

__device__ uint32_t g_kr[N_PTS];
__device__ uint32_t g_hist[NB];
__device__ uint32_t g_off[NB];
__device__ float4   g_xs[N_PTS];
__device__ float4   g_dense4[TOTAL_DENSE / 2];   // float2 entries, 16B aligned

__device__ __forceinline__ uint32_t part1by2(uint32_t v) {
    v &= 0x3FFu;
    v = (v | (v << 16)) & 0x030000FFu;
    v = (v | (v << 8))  & 0x0300F00Fu;
    v = (v | (v << 4))  & 0x030C30C3u;
    v = (v | (v << 2))  & 0x09249249u;
    return v;
}

__device__ __forceinline__ uint32_t bucket_key(float px, float py, float pz) {
    uint32_t cx = min((uint32_t)(px * (float)SORT_RES), (uint32_t)(SORT_RES - 1));
    uint32_t cy = min((uint32_t)(py * (float)SORT_RES), (uint32_t)(SORT_RES - 1));
    uint32_t cz = min((uint32_t)(pz * (float)SORT_RES), (uint32_t)(SORT_RES - 1));
    return part1by2(cx) | (part1by2(cy) << 1) | (part1by2(cz) << 2);
}

__global__ void hist_kernel(const float* __restrict__ x) {
    int i = blockIdx.x * blockDim.x + threadIdx.x;
    if (i >= N_PTS) return;
    uint32_t key = bucket_key(x[3 * i], x[3 * i + 1], x[3 * i + 2]);
    uint32_t rank = atomicAdd(&g_hist[key], 1u);
    g_kr[i] = key | (rank << 15);
}

__device__ __forceinline__ uint32_t swz(uint32_t i) {
    return (i & ~31u) | ((i + (i >> 5)) & 31u);
}

__global__ void __launch_bounds__(1024) scan_kernel() {
    extern __shared__ uint32_t sh[];
    __shared__ uint32_t s[1024];
    const int t = threadIdx.x;

    #pragma unroll
    for (int k = 0; k < 32; k++) {
        uint32_t i = (uint32_t)(k * 1024 + t);
        sh[swz(i)] = g_hist[i];
    }
    __syncthreads();

    uint32_t vals[32];
    uint32_t tot = 0;
    #pragma unroll
    for (int k = 0; k < 32; k++) {
        vals[k] = sh[t * 32 + ((k + t) & 31)];
        tot += vals[k];
    }
    s[t] = tot;
    __syncthreads();

    for (int off = 1; off < 1024; off <<= 1) {
        uint32_t v = (t >= off) ? s[t - off] : 0u;
        __syncthreads();
        s[t] += v;
        __syncthreads();
    }

    uint32_t run = s[t] - tot;
    #pragma unroll
    for (int k = 0; k < 32; k++) {
        sh[t * 32 + ((k + t) & 31)] = run;
        run += vals[k];
    }
    __syncthreads();

    #pragma unroll
    for (int k = 0; k < 32; k++) {
        uint32_t i = (uint32_t)(k * 1024 + t);
        g_off[i] = sh[swz(i)];
    }
}

__global__ void scatter_kernel(const float* __restrict__ x) {
    int i = blockIdx.x * blockDim.x + threadIdx.x;
    if (i >= N_PTS) return;
    uint32_t v = g_kr[i];
    uint32_t pos = g_off[v & (NB - 1u)] + (v >> 15);
    float4 p;
    p.x = x[3 * i + 0];
    p.y = x[3 * i + 1];
    p.z = x[3 * i + 2];
    p.w = __uint_as_float((uint32_t)i);
    __stcs(&g_xs[pos], p);
}

// Dense-grid geometry (levels 0..6): r, Sx=r+2, SxSy=Sx*(r+1), cum. offset.
__device__ __constant__ int      cR[DENSE_LEVELS]    = {16, 22, 30, 42, 58, 80, 110};
__device__ __constant__ int      cSx[DENSE_LEVELS]   = {18, 24, 32, 44, 60, 82, 112};
__device__ __constant__ int      cSxSy[DENSE_LEVELS] = {306, 552, 992, 1892, 3540, 6642, 12432};
__device__ __constant__ uint32_t cOff[DENSE_LEVELS + 1] =
    {0u, 5202u, 17898u, 48650u, 130006u, 338866u, 876868u, 2256820u};

// ONE fused launch re-grids all dense levels:
// dense[off_l + cx + cy*Sx + cz*SxSy] = table[l][hash(cx,cy,cz)]  (verbatim copy)
__global__ void build_dense_kernel(const float* __restrict__ tables) {
    uint32_t i = blockIdx.x * blockDim.x + threadIdx.x;
    if (i >= TOTAL_DENSE) return;

    int l = 0;
    #pragma unroll
    for (int k = 1; k < DENSE_LEVELS; k++)
        if (i >= cOff[k]) l = k;

    uint32_t idx = i - cOff[l];
    uint32_t SxSy = (uint32_t)cSxSy[l];
    uint32_t Sx   = (uint32_t)cSx[l];
    uint32_t cz  = idx / SxSy;
    uint32_t rem = idx - cz * SxSy;
    uint32_t cy  = rem / Sx;
    uint32_t cx  = rem - cy * Sx;
    if (cx > (uint32_t)cR[l]) return;          // padding column, never read

    uint32_t h = (cx ^ (cy * P1) ^ (cz * P2)) & TMASK;
    const float2* __restrict__ tab =
        (const float2*)(tables + (size_t)l * TBL_SIZE * N_FEATURES);
    ((float2*)g_dense4)[i] = __ldg(tab + h);
}

__global__ void __launch_bounds__(256, 5) hashgrid_kernel(
    const float* __restrict__ tables,
    float* __restrict__ out)
{
    const int i = blockIdx.x * blockDim.x + threadIdx.x;
    if (i >= N_PTS) return;

    const float4 p = __ldg(&g_xs[i]);
    const float px = p.x;
    const float py = p.y;
    const float pz = p.z;
    const uint32_t j = __float_as_uint(p.w);

    float4* __restrict__ o = (float4*)(out + (size_t)j * (N_LEVELS * N_FEATURES));

    const int res_host[N_LEVELS] = {16, 22, 30, 42, 58, 80, 110, 152, 210, 290, 400, 553};
    const int dSx[DENSE_LEVELS]   = {18, 24, 32, 44, 60, 82, 112};
    const int dSxSy[DENSE_LEVELS] = {306, 552, 992, 1892, 3540, 6642, 12432};
    const uint32_t dOff[DENSE_LEVELS] =
        {0u, 5202u, 17898u, 48650u, 130006u, 338866u, 876868u};

    const float2* __restrict__ dense  = (const float2*)g_dense4;
    const float4* __restrict__ dense4 = (const float4*)g_dense4;

    float pend0 = 0.0f, pend1 = 0.0f;

    #pragma unroll
    for (int l = 0; l < N_LEVELS; l++) {
        const float res = (float)res_host[l];

        const float sx = px * res;
        const float sy = py * res;
        const float sz = pz * res;
        const float fx = floorf(sx);
        const float fy = floorf(sy);
        const float fz = floorf(sz);
        const float wx = sx - fx;
        const float wy = sy - fy;
        const float wz = sz - fz;

        const uint32_t xi = (uint32_t)fx;
        const uint32_t yi = (uint32_t)fy;
        const uint32_t zi = (uint32_t)fz;

        float2 f000, f100, f010, f110, f001, f101, f011, f111;

        if (l < DENSE_LEVELS) {
            // Spatially-indexed grid: a sorted warp's corners share lines.
            const uint32_t Sx   = (uint32_t)dSx[l];
            const uint32_t SxSy = (uint32_t)dSxSy[l];
            const uint32_t base = dOff[l] + xi + yi * Sx + zi * SxSy;

            const uint32_t b00 = base;
            const uint32_t b10 = base + Sx;
            const uint32_t b01 = base + SxSy;
            const uint32_t b11 = b10 + SxSy;

            if ((xi & 1u) == 0u) {
                // Sx, SxSy, off all even -> even base: dx-pair = aligned float4.
                const float4 v00 = __ldg(dense4 + (b00 >> 1));
                const float4 v10 = __ldg(dense4 + (b10 >> 1));
                const float4 v01 = __ldg(dense4 + (b01 >> 1));
                const float4 v11 = __ldg(dense4 + (b11 >> 1));
                f000 = make_float2(v00.x, v00.y);  f100 = make_float2(v00.z, v00.w);
                f010 = make_float2(v10.x, v10.y);  f110 = make_float2(v10.z, v10.w);
                f001 = make_float2(v01.x, v01.y);  f101 = make_float2(v01.z, v01.w);
                f011 = make_float2(v11.x, v11.y);  f111 = make_float2(v11.z, v11.w);
            } else {
                f000 = __ldg(dense + b00);  f100 = __ldg(dense + b00 + 1);
                f010 = __ldg(dense + b10);  f110 = __ldg(dense + b10 + 1);
                f001 = __ldg(dense + b01);  f101 = __ldg(dense + b01 + 1);
                f011 = __ldg(dense + b11);  f111 = __ldg(dense + b11 + 1);
            }
        } else {
            // Hashed path (levels 7..11)
            const uint32_t hy0 = yi * P1;
            const uint32_t hy1 = (yi + 1u) * P1;
            const uint32_t hz0 = zi * P2;
            const uint32_t hz1 = (zi + 1u) * P2;
            const uint32_t x0 = xi;
            const uint32_t x1 = xi + 1u;

            const uint32_t m00 = hy0 ^ hz0;
            const uint32_t m10 = hy1 ^ hz0;
            const uint32_t m01 = hy0 ^ hz1;
            const uint32_t m11 = hy1 ^ hz1;

            const uint32_t i000 = (x0 ^ m00) & TMASK;
            const uint32_t i010 = (x0 ^ m10) & TMASK;
            const uint32_t i001 = (x0 ^ m01) & TMASK;
            const uint32_t i011 = (x0 ^ m11) & TMASK;

            const float2* __restrict__ tab =
                (const float2*)(tables + (size_t)l * TBL_SIZE * N_FEATURES);

            if ((xi & 1u) == 0u) {
                const float4* __restrict__ t4 = (const float4*)tab;
                const float4 v00 = __ldg(t4 + (i000 >> 1));
                const float4 v10 = __ldg(t4 + (i010 >> 1));
                const float4 v01 = __ldg(t4 + (i001 >> 1));
                const float4 v11 = __ldg(t4 + (i011 >> 1));

                const bool s00 = (i000 & 1u) != 0u;
                const bool s10 = (i010 & 1u) != 0u;
                const bool s01 = (i001 & 1u) != 0u;
                const bool s11 = (i011 & 1u) != 0u;

                f000 = s00 ? make_float2(v00.z, v00.w) : make_float2(v00.x, v00.y);
                f100 = s00 ? make_float2(v00.x, v00.y) : make_float2(v00.z, v00.w);
                f010 = s10 ? make_float2(v10.z, v10.w) : make_float2(v10.x, v10.y);
                f110 = s10 ? make_float2(v10.x, v10.y) : make_float2(v10.z, v10.w);
                f001 = s01 ? make_float2(v01.z, v01.w) : make_float2(v01.x, v01.y);
                f101 = s01 ? make_float2(v01.x, v01.y) : make_float2(v01.z, v01.w);
                f011 = s11 ? make_float2(v11.z, v11.w) : make_float2(v11.x, v11.y);
                f111 = s11 ? make_float2(v11.x, v11.y) : make_float2(v11.z, v11.w);
            } else {
                const uint32_t i100 = (x1 ^ m00) & TMASK;
                const uint32_t i110 = (x1 ^ m10) & TMASK;
                const uint32_t i101 = (x1 ^ m01) & TMASK;
                const uint32_t i111 = (x1 ^ m11) & TMASK;

                f000 = __ldg(tab + i000);
                f100 = __ldg(tab + i100);
                f010 = __ldg(tab + i010);
                f110 = __ldg(tab + i110);
                f001 = __ldg(tab + i001);
                f101 = __ldg(tab + i101);
                f011 = __ldg(tab + i011);
                f111 = __ldg(tab + i111);
            }
        }

        const float ux = 1.0f - wx;
        const float uy = 1.0f - wy;
        const float uz = 1.0f - wz;

        const float w000 = ux * uy * uz;
        const float w100 = wx * uy * uz;
        const float w010 = ux * wy * uz;
        const float w110 = wx * wy * uz;
        const float w001 = ux * uy * wz;
        const float w101 = wx * uy * wz;
        const float w011 = ux * wy * wz;
        const float w111 = wx * wy * wz;

        float acc0 = w000 * f000.x;
        float acc1 = w000 * f000.y;
        acc0 += w100 * f100.x;  acc1 += w100 * f100.y;
        acc0 += w010 * f010.x;  acc1 += w010 * f010.y;
        acc0 += w110 * f110.x;  acc1 += w110 * f110.y;
        acc0 += w001 * f001.x;  acc1 += w001 * f001.y;
        acc0 += w101 * f101.x;  acc1 += w101 * f101.y;
        acc0 += w011 * f011.x;  acc1 += w011 * f011.y;
        acc0 += w111 * f111.x;  acc1 += w111 * f111.y;

        if ((l & 1) == 0) {
            pend0 = acc0;
            pend1 = acc1;
        } else {
            __stcs(&o[l >> 1], make_float4(pend0, pend1, acc0, acc1));
        }
    }
}

extern "C" void kernel_launch(void* const* d_in, const int* in_sizes, int n_in,
                              void* d_out, int out_size) {
    const float* x      = (const float*)d_in[0];
    const float* tables = (const float*)d_in[1];
    float* out          = (float*)d_out;

    const int threads = 256;
    const int blocks = (N_PTS + threads - 1) / threads;

    static bool attr_set = false;
    if (!attr_set) {
        cudaFuncSetAttribute(scan_kernel,
                             cudaFuncAttributeMaxDynamicSharedMemorySize,
                             NB * sizeof(uint32_t));
        attr_set = true;
    }

    void* hist_ptr = nullptr;
    cudaGetSymbolAddress(&hist_ptr, g_hist);
    cudaMemsetAsync(hist_ptr, 0, NB * sizeof(uint32_t));

    // Build runs concurrently with the sort pipeline (independent data).
    build_dense_kernel<<<(TOTAL_DENSE + 255) / 256, 256>>>(tables);

    hist_kernel<<<blocks, threads>>>(x);
    scan_kernel<<<1, 1024, NB * sizeof(uint32_t)>>>();
    scatter_kernel<<<blocks, threads>>>(x);
    hashgrid_kernel<<<blocks, threads>>>(tables, out);
}